// round 13
// baseline (speedup 1.0000x reference)
#include <cuda_runtime.h>
#include <math.h>

#define BSZ 2048
#define TT 8
#define NQ 10
#define FULLM 0xffffffffu

__device__ __forceinline__ float fast_tanh(float x) {
    float y; asm("tanh.approx.f32 %0, %1;" : "=f"(y) : "f"(x)); return y;
}
__device__ __forceinline__ float fast_sigmoid(float x) {
    return 0.5f * fast_tanh(0.5f * x) + 0.5f;
}

// One warp per batch element. 2048 blocks x 32 threads.
// Shared feature layout (16B-aligned bases):
//   [  0.. 35] input features   [ 36.. 71] candidate   [ 72..107] temporal
//   [108..127] forget folded    [132..151] memory folded
__global__ __launch_bounds__(32, 14) void qlstm_kernel(
    const float* __restrict__ x, const float* __restrict__ Wx,
    const float* __restrict__ Wh, const float* __restrict__ bias,
    const float* __restrict__ R, float* __restrict__ out)
{
    __shared__ __align__(16) float sAll[156];

    const int lane = threadIdx.x;
    const int b = blockIdx.x;

    for (int i = lane; i < 156; i += 32) sAll[i] = 0.f;

    // ---- matvec column ownership ----
    int colA = (lane < 30) ? lane : 80;                            // 0..29 | temporal(80)
    int colB;
    if (lane < 20)      colB = 41 + 3 * (lane >> 1) + (lane & 1);  // candidate
    else if (lane < 30) colB = 50 + lane;                          // memory 70..79
    else                colB = 80;

    float wxA[NQ], whA[NQ], wxB[NQ], whB[NQ];
    #pragma unroll
    for (int k = 0; k < NQ; k++) {
        wxA[k] = Wx[k*81 + colA];  whA[k] = Wh[k*81 + colA];
        wxB[k] = Wx[k*81 + colB];  whB[k] = Wh[k*81 + colB];
    }
    const float bA = bias[colA], bB = bias[colB];

    // ---- gate weights in registers ----
    const int n1 = lane % 10;
    float Rp1[20];
    if (lane < 10) {            // forget, folded (f1=f2)
        #pragma unroll
        for (int q = 0; q < NQ; q++) {
            Rp1[2*q]   = R[(3*q)*10 + n1];
            Rp1[2*q+1] = R[(3*q+1)*10 + n1] + R[(3*q+2)*10 + n1];
        }
    } else if (lane < 20) {     // memory, folded (f2=0)
        #pragma unroll
        for (int q = 0; q < NQ; q++) {
            Rp1[2*q]   = R[1200 + (3*q)*10 + n1];
            Rp1[2*q+1] = R[1200 + (3*q+1)*10 + n1];
        }
    } else {
        #pragma unroll
        for (int f = 0; f < 20; f++) Rp1[f] = 0.f;
    }
    float Rp2[32];
    Rp2[30] = 0.f; Rp2[31] = 0.f;
    if (lane < 30) {            // input / candidate / temporal
        int g = lane / 10;
        int base = ((g == 0) ? 1 : ((g == 1) ? 3 : 5)) * 300;
        #pragma unroll
        for (int f = 0; f < 30; f++) Rp2[f] = R[base + f*10 + n1];
    } else {
        #pragma unroll
        for (int f = 0; f < 30; f++) Rp2[f] = 0.f;
    }

    // circ_output constant -> og fixed
    float og = 0.f;
    if (lane < NQ) {
        float G2 = 0.f;
        #pragma unroll
        for (int q = 0; q < NQ; q++) G2 += R[600 + (3*q+1)*10 + lane];
        og = fast_sigmoid(G2);
    }

    // ---- precompute bias + x_t @ Wx for all timesteps into REGISTERS ----
    float pxA[TT], pxB[TT];
    #pragma unroll
    for (int t = 0; t < TT; t++) {
        float xv = (lane < NQ) ? x[(b*TT + t)*NQ + lane] : 0.f;
        float a0 = bA, a1v = 0.f, c0 = bB, c1v = 0.f;
        #pragma unroll
        for (int k = 0; k < NQ; k += 2) {
            float xk0 = __shfl_sync(FULLM, xv, k);
            float xk1 = __shfl_sync(FULLM, xv, k + 1);
            a0  = fmaf(xk0, wxA[k],   a0);
            a1v = fmaf(xk1, wxA[k+1], a1v);
            c0  = fmaf(xk0, wxB[k],   c0);
            c1v = fmaf(xk1, wxB[k+1], c1v);
        }
        pxA[t] = a0 + a1v;
        pxB[t] = c0 + c1v;
    }

    // ---- per-lane shuffle source indices (constant over t) ----
    const bool g0 = lane < 10, g1 = (lane >= 10 && lane < 20), g2 = (lane >= 20 && lane < 30);
    const int iA1 = g1 ? 2*lane - 10 : 0;                     // input col 10+2q
    const int iA2 = g1 ? 2*lane - 9  : 0;                     // input col 11+2q
    const int iB1 = g0 ? 20 + lane : (g2 ? 2*lane - 40 : 0);  // mem col / cand col1
    const int iB2 = g2 ? 2*lane - 39 : 0;                     // cand col2

    const float PIH = 1.57079632679489662f;
    float hv = 0.f, creg = 0.f;

    #pragma unroll
    for (int t = 0; t < TT; t++) {
        // ---- in-loop matvec: h @ Wh, 2-way split accumulator chains ----
        float pA0 = pxA[t], pA1 = 0.f, pB0 = pxB[t], pB1 = 0.f;
        #pragma unroll
        for (int k = 0; k < NQ; k += 2) {
            float hk0 = __shfl_sync(FULLM, hv, k);
            float hk1 = __shfl_sync(FULLM, hv, k + 1);
            pA0 = fmaf(hk0, whA[k],   pA0);
            pA1 = fmaf(hk1, whA[k+1], pA1);
            pB0 = fmaf(hk0, whB[k],   pB0);
            pB1 = fmaf(hk1, whB[k+1], pB1);
        }
        float pA = pA0 + pA1, pB = pB0 + pB1;

        float a1 = __shfl_sync(FULLM, pA, iA1);
        float a2 = __shfl_sync(FULLM, pA, iA2);
        float b1 = __shfl_sync(FULLM, pB, iB1);
        float b2v = __shfl_sync(FULLM, pB, iB2);
        float tp = __shfl_sync(FULLM, pA, 30);

        // ---- pass A (branchless, lanes 0..29): generic pz/xr/xi ----
        // forget: alpha=pA, beta=0 ; input: alpha=a1, beta=a2 ;
        // candidate: alpha=b1-pi/2, beta=b2 (pz=-sin(b1-pi/2)=cos b1, etc.)
        float alpha = g0 ? pA : (g1 ? a1 : b1 - PIH);
        float beta  = g1 ? a2 : (g2 ? b2v : 0.f);
        float s1, c1; __sincosf(alpha, &s1, &c1);
        float s2, c2; __sincosf(beta,  &s2, &c2);
        float pz = -s1;
        float xr = 0.5f * c1 * c2;
        float xi = 0.5f * c1 * s2;

        // ---- pass A couplings (short divergent segments) ----
        if (g0) {                               // forget: T + CZ pairs (folded f1=f2)
            float pzn = __shfl_xor_sync(0x3FFu, pz, 1);
            sAll[108 + 2*lane] = pz;
            sAll[109 + 2*lane] = 1.41421356237f * xr * pzn;
        } else if (g1) {                        // input: CNOT chain (shuffle scan)
            int q = lane - 10;
            float incl = pz;
            #pragma unroll
            for (int d = 1; d < 10; d <<= 1) {
                float tv = __shfl_up_sync(0xFFC00u, incl, d);
                if (q >= d) incl *= tv;
            }
            float ex = __shfl_up_sync(0xFFC00u, incl, 1);
            if (q == 0) ex = 1.f;
            float xrn = __shfl_down_sync(0xFFC00u, xr, 1);
            float C = (q < 9) ? 2.f * xrn : 1.f;
            sAll[3*q]   = incl;
            sAll[3*q+1] = 2.f * C * xr;
            sAll[3*q+2] = 2.f * C * xi * ex;
        } else if (g2) {                        // candidate: CAND_CZ mask products
            int q = lane - 20;
            const int MASK[10] = {0x304,0x48,0x2F9,0x86,0x44,0x204,0x16,0xC,0x1,0x25};
            float prod = 1.f;
            #pragma unroll
            for (int j = 0; j < NQ; j++) {
                float pj = __shfl_sync(0x3FF00000u, pz, 20 + j);
                if ((MASK[j] >> q) & 1) prod *= pj;
            }
            sAll[36 + 3*q] = pz;
            sAll[37 + 3*q] = 2.f * xr * prod;
            sAll[38 + 3*q] = 2.f * xi * prod;
        }

        // ---- pass B: memory (lanes 0-9) / temporal (lanes 10-19) ----
        if (g0) {                               // memory: RY; CZ pairs (folded f2=0)
            float sn2, cs2; __sincosf(b1, &sn2, &cs2);
            float pz2 = -sn2, xr2 = 0.5f * cs2;
            float pzn2 = __shfl_xor_sync(0x3FFu, pz2, 1);
            sAll[132 + 2*lane] = pz2;
            sAll[133 + 2*lane] = 2.f * xr2 * pzn2;
        } else if (g1) {                        // temporal: RX(0.05t)*RZ(0.1t); ZZ sandwich
            int q = lane - 10;
            float a = 0.1f * tp, bb = 0.05f * tp;
            float SB, CB; __sincosf(0.5f * bb, &SB, &CB);
            float pzT, xrT, xiT;
            if (q == 0) {                       // qubit 0 in |0>
                pzT = CB*CB - SB*SB; xrT = 0.f; xiT = -CB*SB;
            } else {                            // |+> input
                float SA, CA; __sincosf(0.5f * a, &SA, &CA);
                const float RS = 0.70710678118654752f;
                float v0r = (CB*CA + SB*SA)*RS, v0i = -(CB*SA + SB*CA)*RS;
                float v1r = (CB*CA - SB*SA)*RS, v1i = (CB*SA - SB*CA)*RS;
                pzT = v0r*v0r + v0i*v0i - v1r*v1r - v1i*v1i;
                xrT = v0r*v1r + v0i*v1i;
                xiT = v0r*v1i - v0i*v1r;
            }
            float s2z, c2z; __sincosf(0.2f * tp, &s2z, &c2z);
            float pzm = __shfl_up_sync(0xFFC00u, pzT, 1);
            float pzp = __shfl_down_sync(0xFFC00u, pzT, 1);
            float er = 1.f, ei = 0.f;
            if (q > 0) { er = c2z; ei = s2z * pzm; }
            if (q < 9) {
                float fr = c2z, fi = s2z * pzp;
                float nr = er*fr - ei*fi, ni = er*fi + ei*fr;
                er = nr; ei = ni;
            }
            sAll[72 + 3*q] = pzT;
            sAll[73 + 3*q] = 2.f * (xrT*er - xiT*ei);
            sAll[74 + 3*q] = 2.f * (xrT*ei + xiT*er);
        }
        __syncwarp();

        // ---- gates: LDS.128 broadcasts + register R, 4-way accumulators ----
        float4 A1 = make_float4(0.f, 0.f, 0.f, 0.f);
        {
            const float4* F1 = (const float4*)(sAll + (g0 ? 108 : 132));
            #pragma unroll
            for (int i = 0; i < 5; i++) {
                float4 fv = F1[i];
                A1.x = fmaf(fv.x, Rp1[4*i],   A1.x);
                A1.y = fmaf(fv.y, Rp1[4*i+1], A1.y);
                A1.z = fmaf(fv.z, Rp1[4*i+2], A1.z);
                A1.w = fmaf(fv.w, Rp1[4*i+3], A1.w);
            }
        }
        float gp1 = (A1.x + A1.y) + (A1.z + A1.w);

        float4 A2 = make_float4(0.f, 0.f, 0.f, 0.f);
        {
            int gidx = (lane < 30) ? lane / 10 : 0;
            const float4* F2 = (const float4*)(sAll + 36*gidx);
            #pragma unroll
            for (int i = 0; i < 8; i++) {
                float4 fv = F2[i];
                A2.x = fmaf(fv.x, Rp2[4*i],   A2.x);
                A2.y = fmaf(fv.y, Rp2[4*i+1], A2.y);
                A2.z = fmaf(fv.z, Rp2[4*i+2], A2.z);
                A2.w = fmaf(fv.w, Rp2[4*i+3], A2.w);
            }
        }
        float gp2 = (A2.x + A2.y) + (A2.z + A2.w);

        // ---- gather gates to lanes 0..9, update cell ----
        float mqv = __shfl_sync(FULLM, gp1, lane + 10);
        float ggv = __shfl_sync(FULLM, gp2, lane + 10);
        float tmv = __shfl_sync(FULLM, gp2, lane + 20);
        float hn = 0.f;
        if (lane < NQ) {
            float fg = fast_sigmoid(gp1);
            float ig = fast_sigmoid(gp2);
            float mq = fast_sigmoid(mqv);
            float gg = fast_tanh(ggv);
            float tm = fast_tanh(tmv);
            float cn = (fg * creg + ig * gg) * mq;
            hn = og * fast_tanh(cn) + 0.1f * tm;
            creg = cn;
            out[(b*TT + t)*NQ + lane] = hn;
        }
        hv = hn;
    }
}

extern "C" void kernel_launch(void* const* d_in, const int* in_sizes, int n_in,
                              void* d_out, int out_size)
{
    const float* x    = (const float*)d_in[0];
    const float* Wx   = (const float*)d_in[1];
    const float* Wh   = (const float*)d_in[2];
    const float* bias = (const float*)d_in[3];
    const float* R    = (const float*)d_in[4];
    float* out = (float*)d_out;

    qlstm_kernel<<<BSZ, 32>>>(x, Wx, Wh, bias, R, out);
}